// round 14
// baseline (speedup 1.0000x reference)
#include <cuda_runtime.h>
#include <cuda_fp16.h>
#include <math.h>

// ---------------- problem constants ----------------
#define N_USER   100000
#define N_ITEM   50000
#define NTOT     (N_USER + N_ITEM)     // 150000
#define EMB      64
#define FEAT     384
#define NNZ      2400000
#define N_PROMPT 8
#define N_LAYERS 4
#define EPS_     1e-8f

#define SCAN_BLK 256
#define NB_SCAN  ((NTOT + SCAN_BLK - 1) / SCAN_BLK)   // 586
#define DBINS    512

// ---------------- device scratch (static, no runtime alloc) ----------------
__device__ float  g_ego [NTOT * EMB];     // layer-0 embeddings, fp32
__device__ __half g_hEgo[NTOT * EMB];     // half copy of ego (gather table L0)
__device__ uint4  g_h1  [NTOT * 8];       // x1 (half rows: 8 x uint4 = 64 half)
__device__ uint4  g_h2  [NTOT * 8];       // x2
__device__ uint4  g_h3  [NTOT * 8];       // x3
__device__ float  g_norm[NTOT];           // ||ego|| per row
__device__ int    g_deg   [NTOT];         // zero at entry; re-zeroed by k_scan1
__device__ int    g_rowptr[NTOT + 1];
__device__ int    g_cursor[NTOT];
__device__ int    g_bsums [1024];
__device__ int    g_boffs [1024];
__device__ int    g_dbin  [DBINS];        // degree histogram (self-resetting)
__device__ int    g_doff  [DBINS];        // degree-bin offsets (rebuilt each call)
__device__ int    g_order [NTOT];         // rows sorted by degree
__device__ int2   g_edges [NNZ];          // {col, float-bits(val)} per edge

// ---------------- 1) user ego = user_fea + prompt-sum (fused) --------------
__global__ void k_user_ego(const float* __restrict__ uf,
                           const float* __restrict__ pe) {
    int i = blockIdx.x * blockDim.x + threadIdx.x;
    if (i >= N_USER * EMB) return;
    int c = i & (EMB - 1);
    float s = 0.f;
    #pragma unroll
    for (int p = 0; p < N_PROMPT; ++p) s += __ldg(&pe[p * EMB + c]);
    float v = uf[i] + s;
    g_ego[i]  = v;
    g_hEgo[i] = __float2half(v);
}

// ---------------- 2) item GEMM + tanh -> ego (fp32 + half copy) ------------
__global__ __launch_bounds__(256) void k_gemm(const float* __restrict__ A,
                                              const float* __restrict__ B,
                                              const float* __restrict__ bias)
{
    __shared__ float As[64][32];
    __shared__ float Bs[32][64];

    const int t     = threadIdx.x;
    const int c     = t & 63;
    const int rq    = t >> 6;
    const int row0  = blockIdx.x * 64;

    float acc[16];
    #pragma unroll
    for (int j = 0; j < 16; ++j) acc[j] = 0.f;

    for (int k0 = 0; k0 < FEAT; k0 += 32) {
        #pragma unroll
        for (int i = 0; i < 8; ++i) {
            int lin = i * 256 + t;
            int r = lin >> 5, k = lin & 31;
            int gr = row0 + r;
            As[r][k] = (gr < N_ITEM) ? A[gr * FEAT + k0 + k] : 0.f;
        }
        #pragma unroll
        for (int i = 0; i < 8; ++i) {
            int lin = i * 256 + t;
            int k = lin >> 6, cc = lin & 63;
            Bs[k][cc] = B[(k0 + k) * EMB + cc];
        }
        __syncthreads();

        float bv[32];
        #pragma unroll
        for (int kk = 0; kk < 32; ++kk) bv[kk] = Bs[kk][c];

        #pragma unroll
        for (int j = 0; j < 16; ++j) {
            const float4* ar = (const float4*)&As[rq * 16 + j][0];
            #pragma unroll
            for (int q = 0; q < 8; ++q) {
                float4 a = ar[q];
                acc[j] += a.x * bv[4*q] + a.y * bv[4*q+1]
                        + a.z * bv[4*q+2] + a.w * bv[4*q+3];
            }
        }
        __syncthreads();
    }

    float bb = bias[c];
    #pragma unroll
    for (int j = 0; j < 16; ++j) {
        int row = row0 + rq * 16 + j;
        if (row < N_ITEM) {
            float v = tanhf(acc[j] + bb);
            g_ego [(N_USER + row) * EMB + c] = v;
            g_hEgo[(N_USER + row) * EMB + c] = __float2half(v);
        }
    }
}

// ---------------- CSR build ----------------
__global__ void k_hist(const int* __restrict__ rows) {
    int e = blockIdx.x * blockDim.x + threadIdx.x;
    if (e < NNZ) atomicAdd(&g_deg[rows[e]], 1);
}
// Local scan + self-zero deg + warp-aggregated degree histogram.
__global__ void k_scan1() {
    __shared__ int sh[SCAN_BLK];
    int t = threadIdx.x;
    int idx = blockIdx.x * SCAN_BLK + t;
    int v = (idx < NTOT) ? g_deg[idx] : 0;
    if (idx < NTOT) g_deg[idx] = 0;                 // reset for next call
    sh[t] = v;

    // warp-aggregated degree histogram (one atomic per distinct degree/warp)
    unsigned act = __ballot_sync(0xffffffffu, idx < NTOT);
    if (idx < NTOT) {
        int d = v < (DBINS - 1) ? v : (DBINS - 1);
        unsigned m = __match_any_sync(act, d);
        int rank = __popc(m & ((1u << (t & 31)) - 1u));
        if (rank == 0) atomicAdd(&g_dbin[d], __popc(m));
    }

    __syncthreads();
    for (int off = 1; off < SCAN_BLK; off <<= 1) {
        int add = (t >= off) ? sh[t - off] : 0;
        __syncthreads();
        sh[t] += add;
        __syncthreads();
    }
    if (idx < NTOT) g_rowptr[idx] = sh[t] - v;      // local exclusive prefix
    if (t == SCAN_BLK - 1) g_bsums[blockIdx.x] = sh[t];
}
// 1 block: scans block sums AND the degree histogram (resetting it).
__global__ void k_scan2() {
    __shared__ int sh[1024];
    int t = threadIdx.x;
    int v = (t < NB_SCAN) ? g_bsums[t] : 0;
    sh[t] = v;
    __syncthreads();
    for (int off = 1; off < 1024; off <<= 1) {
        int add = (t >= off) ? sh[t - off] : 0;
        __syncthreads();
        sh[t] += add;
        __syncthreads();
    }
    if (t < NB_SCAN) g_boffs[t] = sh[t] - v;         // exclusive block offsets
    if (t == 1023)   g_rowptr[NTOT] = sh[1023];      // == NNZ
    __syncthreads();

    // scan degree histogram (512 bins) -> g_doff, reset g_dbin
    int dv = (t < DBINS) ? g_dbin[t] : 0;
    if (t < DBINS) g_dbin[t] = 0;
    sh[t] = dv;
    __syncthreads();
    for (int off = 1; off < DBINS; off <<= 1) {
        int add = (t >= off && t < DBINS) ? sh[t - off] : 0;
        __syncthreads();
        if (t < DBINS) sh[t] += add;
        __syncthreads();
    }
    if (t < DBINS) g_doff[t] = sh[t] - dv;           // exclusive bin offsets
}
__global__ void k_scan3() {
    int i = blockIdx.x * blockDim.x + threadIdx.x;
    if (i < NTOT) {
        int r = g_rowptr[i] + g_boffs[i >> 8];
        g_rowptr[i] = r;
        g_cursor[i] = r;
    }
}
// Scatter row ids into degree-sorted order (warp-aggregated atomics).
__global__ void k_dorder() {
    int i = blockIdx.x * blockDim.x + threadIdx.x;
    unsigned act = __ballot_sync(0xffffffffu, i < NTOT);
    if (i >= NTOT) return;
    int d = g_rowptr[i + 1] - g_rowptr[i];
    if (d > DBINS - 1) d = DBINS - 1;
    unsigned m = __match_any_sync(act, d);
    int lane = threadIdx.x & 31;
    int leader = __ffs(m) - 1;
    int rank = __popc(m & ((1u << lane) - 1u));
    int base = 0;
    if (lane == leader) base = atomicAdd(&g_doff[d], __popc(m));
    base = __shfl_sync(m, base, leader);
    g_order[base + rank] = i;
}
__global__ void k_scatter(const int* __restrict__ rows,
                          const int* __restrict__ cols,
                          const float* __restrict__ vals) {
    int e = blockIdx.x * blockDim.x + threadIdx.x;
    if (e < NNZ) {
        int p = atomicAdd(&g_cursor[rows[e]], 1);
        g_edges[p] = make_int2(cols[e], __float_as_int(vals[e]));
    }
}

// ---------------- helpers: 16B of halfs <-> 8 floats ----------------
__device__ __forceinline__ void h16_to_f8(uint4 r, float* f) {
    float2 t;
    t = __half22float2(*(__half2*)&r.x); f[0] = t.x; f[1] = t.y;
    t = __half22float2(*(__half2*)&r.y); f[2] = t.x; f[3] = t.y;
    t = __half22float2(*(__half2*)&r.z); f[4] = t.x; f[5] = t.y;
    t = __half22float2(*(__half2*)&r.w); f[6] = t.x; f[7] = t.y;
}
__device__ __forceinline__ uint4 f8_to_h16(const float* f) {
    uint4 r; __half2 h;
    h = __floats2half2_rn(f[0], f[1]); r.x = *(unsigned*)&h;
    h = __floats2half2_rn(f[2], f[3]); r.y = *(unsigned*)&h;
    h = __floats2half2_rn(f[4], f[5]); r.z = *(unsigned*)&h;
    h = __floats2half2_rn(f[6], f[7]); r.w = *(unsigned*)&h;
    return r;
}

// ---------------- fused propagate layer (4 rows/warp, degree-binned) -------
// Rows are taken from g_order (degree-sorted) so a warp's 4 rows have
// near-identical trip counts -> masked-iteration waste eliminated.
template<bool FIRST, bool LAST>
__global__ __launch_bounds__(256) void k_prop(const uint4* __restrict__ xh,
                                              uint4* __restrict__ xn,
                                              float4* __restrict__ out)
{
    const unsigned FULL = 0xffffffffu;
    int warp = (blockIdx.x * blockDim.x + threadIdx.x) >> 5;
    int lane = threadIdx.x & 31;
    int hl   = lane & 7;
    int slot = warp * 4 + (lane >> 3);
    if (slot >= NTOT) return;
    int row  = g_order[slot];

    int beg = g_rowptr[row];
    int end = g_rowptr[row + 1];

    float acc[8];
    #pragma unroll
    for (int k = 0; k < 8; ++k) acc[k] = 0.f;

    int e = beg;
    for (; e + 4 <= end; e += 4) {
        int2 e0 = g_edges[e+0];
        int2 e1 = g_edges[e+1];
        int2 e2 = g_edges[e+2];
        int2 e3 = g_edges[e+3];
        uint4 r0 = xh[e0.x * 8 + hl];
        uint4 r1 = xh[e1.x * 8 + hl];
        uint4 r2 = xh[e2.x * 8 + hl];
        uint4 r3 = xh[e3.x * 8 + hl];
        float x0[8], x1[8], x2[8], x3[8];
        h16_to_f8(r0, x0);
        h16_to_f8(r1, x1);
        h16_to_f8(r2, x2);
        h16_to_f8(r3, x3);
        float v0 = __int_as_float(e0.y);
        float v1 = __int_as_float(e1.y);
        float v2 = __int_as_float(e2.y);
        float v3 = __int_as_float(e3.y);
        #pragma unroll
        for (int k = 0; k < 8; ++k)
            acc[k] += v0*x0[k] + v1*x1[k] + v2*x2[k] + v3*x3[k];
    }
    for (; e < end; ++e) {
        int2  cv = g_edges[e];
        float v  = __int_as_float(cv.y);
        uint4 rr = xh[cv.x * 8 + hl];
        float xv[8];
        h16_to_f8(rr, xv);
        #pragma unroll
        for (int k = 0; k < 8; ++k) acc[k] += v * xv[k];
    }

    const float4* egof = (const float4*)g_ego;
    float4 ea = egof[row * 16 + hl * 2];
    float4 eb = egof[row * 16 + hl * 2 + 1];
    float eg[8] = {ea.x, ea.y, ea.z, ea.w, eb.x, eb.y, eb.z, eb.w};

    float dot = 0.f, nrm = 0.f, egn = 0.f;
    #pragma unroll
    for (int k = 0; k < 8; ++k) {
        dot += acc[k] * eg[k];
        nrm += acc[k] * acc[k];
        if (FIRST) egn += eg[k] * eg[k];
    }
    #pragma unroll
    for (int o = 4; o; o >>= 1) {
        dot += __shfl_xor_sync(FULL, dot, o);
        nrm += __shfl_xor_sync(FULL, nrm, o);
        if (FIRST) egn += __shfl_xor_sync(FULL, egn, o);
    }

    float ego_norm;
    if (FIRST) {
        ego_norm = sqrtf(egn);
        if (hl == 0) g_norm[row] = ego_norm;
    } else {
        ego_norm = g_norm[row];
    }
    float w = dot / fmaxf(sqrtf(nrm) * ego_norm, EPS_);

    float r[8];
    #pragma unroll
    for (int k = 0; k < 8; ++k) r[k] = w * acc[k];

    if (LAST) {
        float s1[8], s2[8], s3[8];
        h16_to_f8(g_h1[row * 8 + hl], s1);
        h16_to_f8(g_h2[row * 8 + hl], s2);
        h16_to_f8(g_h3[row * 8 + hl], s3);
        float o0[8];
        #pragma unroll
        for (int k = 0; k < 8; ++k)
            o0[k] = eg[k] + s1[k] + s2[k] + s3[k] + r[k];
        out[row * 16 + hl * 2]     = make_float4(o0[0], o0[1], o0[2], o0[3]);
        out[row * 16 + hl * 2 + 1] = make_float4(o0[4], o0[5], o0[6], o0[7]);
    } else {
        xn[row * 8 + hl] = f8_to_h16(r);
    }
}

// ---------------- launch ----------------
extern "C" void kernel_launch(void* const* d_in, const int* in_sizes, int n_in,
                              void* d_out, int out_size)
{
    const float* user_fea = (const float*)d_in[0];
    const float* item_fea = (const float*)d_in[1];
    const float* prompt   = (const float*)d_in[2];
    const float* mlp_w    = (const float*)d_in[3];
    const float* mlp_b    = (const float*)d_in[4];
    const int*   adj_rows = (const int*)  d_in[5];
    const int*   adj_cols = (const int*)  d_in[6];
    const float* adj_vals = (const float*)d_in[7];
    float* out = (float*)d_out;

    static cudaStream_t s2 = nullptr;
    static cudaEvent_t  evFork = nullptr, evJoin = nullptr;
    if (s2 == nullptr) {
        cudaStreamCreateWithFlags(&s2, cudaStreamNonBlocking);
        cudaEventCreateWithFlags(&evFork, cudaEventDisableTiming);
        cudaEventCreateWithFlags(&evJoin, cudaEventDisableTiming);
    }

    uint4 *hEgo = nullptr, *h1 = nullptr, *h2 = nullptr, *h3 = nullptr;
    cudaGetSymbolAddress((void**)&hEgo, g_hEgo);
    cudaGetSymbolAddress((void**)&h1, g_h1);
    cudaGetSymbolAddress((void**)&h2, g_h2);
    cudaGetSymbolAddress((void**)&h3, g_h3);
    float4* out4 = (float4*)out;

    // ---- fork: CSR build on s2, embeddings on capture (default) stream ----
    cudaEventRecord(evFork, 0);
    cudaStreamWaitEvent(s2, evFork, 0);

    // branch A (default stream): embeddings
    k_user_ego<<<(N_USER * EMB + 255) / 256, 256>>>(user_fea, prompt);
    k_gemm    <<<(N_ITEM + 63) / 64, 256>>>(item_fea, mlp_w, mlp_b);

    // branch B (s2): CSR build + degree-sorted row order
    k_hist    <<<(NNZ + 255) / 256, 256, 0, s2>>>(adj_rows);
    k_scan1   <<<NB_SCAN, SCAN_BLK, 0, s2>>>();
    k_scan2   <<<1, 1024, 0, s2>>>();
    k_scan3   <<<(NTOT + 255) / 256, 256, 0, s2>>>();
    k_dorder  <<<(NTOT + 255) / 256, 256, 0, s2>>>();
    k_scatter <<<(NNZ + 255) / 256, 256, 0, s2>>>(adj_rows, adj_cols, adj_vals);

    // ---- join ----
    cudaEventRecord(evJoin, s2);
    cudaStreamWaitEvent(0, evJoin, 0);

    // --- 4 propagation layers; last layer fuses the output epilogue ---
    int nwarp   = (NTOT + 3) / 4;                      // 4 rows per warp
    int pblocks = (nwarp * 32 + 255) / 256;
    k_prop<true,  false><<<pblocks, 256>>>(hEgo, h1, nullptr);
    k_prop<false, false><<<pblocks, 256>>>(h1,   h2, nullptr);
    k_prop<false, false><<<pblocks, 256>>>(h2,   h3, nullptr);
    k_prop<false, true ><<<pblocks, 256>>>(h3,   nullptr, out4);
}

// round 15
// speedup vs baseline: 1.4500x; 1.4500x over previous
#include <cuda_runtime.h>
#include <cuda_fp16.h>
#include <math.h>

// ---------------- problem constants ----------------
#define N_USER   100000
#define N_ITEM   50000
#define NTOT     (N_USER + N_ITEM)     // 150000
#define EMB      64
#define FEAT     384
#define NNZ      2400000
#define N_PROMPT 8
#define N_LAYERS 4
#define EPS_     1e-8f

#define SCAN_BLK 256
#define NB_SCAN  ((NTOT + SCAN_BLK - 1) / SCAN_BLK)   // 586

// ---------------- device scratch (static, no runtime alloc) ----------------
__device__ float  g_ego [NTOT * EMB];     // layer-0 embeddings, fp32
__device__ __half g_hEgo[NTOT * EMB];     // half copy of ego (gather table L0)
__device__ uint4  g_h1  [NTOT * 8];       // x1 (half rows: 8 x uint4 = 64 half)
__device__ uint4  g_h2  [NTOT * 8];       // x2
__device__ uint4  g_h3  [NTOT * 8];       // x3
__device__ float  g_norm[NTOT];           // ||ego|| per row
__device__ int    g_deg   [NTOT];         // zero at entry; re-zeroed by k_scan1
__device__ int    g_rowptr[NTOT + 1];
__device__ int    g_cursor[NTOT];
__device__ int    g_bsums [1024];
__device__ int    g_boffs [1024];
__device__ int2   g_edges [NNZ];          // {col, float-bits(val)} per edge

// ---------------- 1) user ego = user_fea + prompt-sum (fused) --------------
__global__ void k_user_ego(const float* __restrict__ uf,
                           const float* __restrict__ pe) {
    int i = blockIdx.x * blockDim.x + threadIdx.x;
    if (i >= N_USER * EMB) return;
    int c = i & (EMB - 1);
    float s = 0.f;
    #pragma unroll
    for (int p = 0; p < N_PROMPT; ++p) s += __ldg(&pe[p * EMB + c]);
    float v = uf[i] + s;
    g_ego[i]  = v;
    g_hEgo[i] = __float2half(v);
}

// ---------------- 2) item GEMM + tanh -> ego (fp32 + half copy) ------------
__global__ __launch_bounds__(256) void k_gemm(const float* __restrict__ A,
                                              const float* __restrict__ B,
                                              const float* __restrict__ bias)
{
    __shared__ float As[64][32];
    __shared__ float Bs[32][64];

    const int t     = threadIdx.x;
    const int c     = t & 63;
    const int rq    = t >> 6;
    const int row0  = blockIdx.x * 64;

    float acc[16];
    #pragma unroll
    for (int j = 0; j < 16; ++j) acc[j] = 0.f;

    for (int k0 = 0; k0 < FEAT; k0 += 32) {
        #pragma unroll
        for (int i = 0; i < 8; ++i) {
            int lin = i * 256 + t;
            int r = lin >> 5, k = lin & 31;
            int gr = row0 + r;
            As[r][k] = (gr < N_ITEM) ? A[gr * FEAT + k0 + k] : 0.f;
        }
        #pragma unroll
        for (int i = 0; i < 8; ++i) {
            int lin = i * 256 + t;
            int k = lin >> 6, cc = lin & 63;
            Bs[k][cc] = B[(k0 + k) * EMB + cc];
        }
        __syncthreads();

        float bv[32];
        #pragma unroll
        for (int kk = 0; kk < 32; ++kk) bv[kk] = Bs[kk][c];

        #pragma unroll
        for (int j = 0; j < 16; ++j) {
            const float4* ar = (const float4*)&As[rq * 16 + j][0];
            #pragma unroll
            for (int q = 0; q < 8; ++q) {
                float4 a = ar[q];
                acc[j] += a.x * bv[4*q] + a.y * bv[4*q+1]
                        + a.z * bv[4*q+2] + a.w * bv[4*q+3];
            }
        }
        __syncthreads();
    }

    float bb = bias[c];
    #pragma unroll
    for (int j = 0; j < 16; ++j) {
        int row = row0 + rq * 16 + j;
        if (row < N_ITEM) {
            float v = tanhf(acc[j] + bb);
            g_ego [(N_USER + row) * EMB + c] = v;
            g_hEgo[(N_USER + row) * EMB + c] = __float2half(v);
        }
    }
}

// ---------------- CSR build (R13 chain; edge kernels vectorized x4) --------
__global__ void k_hist(const int4* __restrict__ rows4) {
    int i = blockIdx.x * blockDim.x + threadIdx.x;
    if (i < NNZ / 4) {
        int4 r = rows4[i];
        atomicAdd(&g_deg[r.x], 1);
        atomicAdd(&g_deg[r.y], 1);
        atomicAdd(&g_deg[r.z], 1);
        atomicAdd(&g_deg[r.w], 1);
    }
}
__global__ void k_scan1() {
    __shared__ int sh[SCAN_BLK];
    int t = threadIdx.x;
    int idx = blockIdx.x * SCAN_BLK + t;
    int v = (idx < NTOT) ? g_deg[idx] : 0;
    if (idx < NTOT) g_deg[idx] = 0;                 // reset for next call
    sh[t] = v;
    __syncthreads();
    for (int off = 1; off < SCAN_BLK; off <<= 1) {
        int add = (t >= off) ? sh[t - off] : 0;
        __syncthreads();
        sh[t] += add;
        __syncthreads();
    }
    if (idx < NTOT) g_rowptr[idx] = sh[t] - v;      // local exclusive prefix
    if (t == SCAN_BLK - 1) g_bsums[blockIdx.x] = sh[t];
}
__global__ void k_scan2() {                          // 1 block, 1024 threads
    __shared__ int sh[1024];
    int t = threadIdx.x;
    int v = (t < NB_SCAN) ? g_bsums[t] : 0;
    sh[t] = v;
    __syncthreads();
    for (int off = 1; off < 1024; off <<= 1) {
        int add = (t >= off) ? sh[t - off] : 0;
        __syncthreads();
        sh[t] += add;
        __syncthreads();
    }
    if (t < NB_SCAN) g_boffs[t] = sh[t] - v;         // exclusive block offsets
    if (t == 1023)   g_rowptr[NTOT] = sh[1023];      // == NNZ
}
__global__ void k_scan3() {
    int i = blockIdx.x * blockDim.x + threadIdx.x;
    if (i < NTOT) {
        int r = g_rowptr[i] + g_boffs[i >> 8];
        g_rowptr[i] = r;
        g_cursor[i] = r;
    }
}
__global__ void k_scatter(const int4* __restrict__ rows4,
                          const int4* __restrict__ cols4,
                          const float4* __restrict__ vals4) {
    int i = blockIdx.x * blockDim.x + threadIdx.x;
    if (i < NNZ / 4) {
        int4   r = rows4[i];
        int4   c = cols4[i];
        float4 w = vals4[i];
        int p0 = atomicAdd(&g_cursor[r.x], 1);
        g_edges[p0] = make_int2(c.x, __float_as_int(w.x));
        int p1 = atomicAdd(&g_cursor[r.y], 1);
        g_edges[p1] = make_int2(c.y, __float_as_int(w.y));
        int p2 = atomicAdd(&g_cursor[r.z], 1);
        g_edges[p2] = make_int2(c.z, __float_as_int(w.z));
        int p3 = atomicAdd(&g_cursor[r.w], 1);
        g_edges[p3] = make_int2(c.w, __float_as_int(w.w));
    }
}

// ---------------- helpers: 16B of halfs <-> 8 floats ----------------
__device__ __forceinline__ void h16_to_f8(uint4 r, float* f) {
    float2 t;
    t = __half22float2(*(__half2*)&r.x); f[0] = t.x; f[1] = t.y;
    t = __half22float2(*(__half2*)&r.y); f[2] = t.x; f[3] = t.y;
    t = __half22float2(*(__half2*)&r.z); f[4] = t.x; f[5] = t.y;
    t = __half22float2(*(__half2*)&r.w); f[6] = t.x; f[7] = t.y;
}
__device__ __forceinline__ uint4 f8_to_h16(const float* f) {
    uint4 r; __half2 h;
    h = __floats2half2_rn(f[0], f[1]); r.x = *(unsigned*)&h;
    h = __floats2half2_rn(f[2], f[3]); r.y = *(unsigned*)&h;
    h = __floats2half2_rn(f[4], f[5]); r.z = *(unsigned*)&h;
    h = __floats2half2_rn(f[6], f[7]); r.w = *(unsigned*)&h;
    return r;
}

// ---------------- fused propagate layer (4 rows per warp) ----------------
// A half row = 64 half = 8 lanes x uint4(16B); warp quarters process 4 rows
// in natural row order (preserves streaming locality on ego/xn/out).
// FIRST: also computes ||ego|| -> g_norm.
// LAST:  writes out = ego + x1 + x2 + x3 + r (fused epilogue).
template<bool FIRST, bool LAST>
__global__ __launch_bounds__(256) void k_prop(const uint4* __restrict__ xh,
                                              uint4* __restrict__ xn,
                                              float4* __restrict__ out)
{
    const unsigned FULL = 0xffffffffu;
    int warp = (blockIdx.x * blockDim.x + threadIdx.x) >> 5;
    int lane = threadIdx.x & 31;
    int hl   = lane & 7;
    int row  = warp * 4 + (lane >> 3);
    if (row >= NTOT) return;

    int beg = g_rowptr[row];
    int end = g_rowptr[row + 1];

    float acc[8];
    #pragma unroll
    for (int k = 0; k < 8; ++k) acc[k] = 0.f;

    int e = beg;
    for (; e + 4 <= end; e += 4) {
        int2 e0 = g_edges[e+0];
        int2 e1 = g_edges[e+1];
        int2 e2 = g_edges[e+2];
        int2 e3 = g_edges[e+3];
        uint4 r0 = xh[e0.x * 8 + hl];
        uint4 r1 = xh[e1.x * 8 + hl];
        uint4 r2 = xh[e2.x * 8 + hl];
        uint4 r3 = xh[e3.x * 8 + hl];
        float x0[8], x1[8], x2[8], x3[8];
        h16_to_f8(r0, x0);
        h16_to_f8(r1, x1);
        h16_to_f8(r2, x2);
        h16_to_f8(r3, x3);
        float v0 = __int_as_float(e0.y);
        float v1 = __int_as_float(e1.y);
        float v2 = __int_as_float(e2.y);
        float v3 = __int_as_float(e3.y);
        #pragma unroll
        for (int k = 0; k < 8; ++k)
            acc[k] += v0*x0[k] + v1*x1[k] + v2*x2[k] + v3*x3[k];
    }
    for (; e < end; ++e) {
        int2  cv = g_edges[e];
        float v  = __int_as_float(cv.y);
        uint4 rr = xh[cv.x * 8 + hl];
        float xv[8];
        h16_to_f8(rr, xv);
        #pragma unroll
        for (int k = 0; k < 8; ++k) acc[k] += v * xv[k];
    }

    const float4* egof = (const float4*)g_ego;
    float4 ea = egof[row * 16 + hl * 2];
    float4 eb = egof[row * 16 + hl * 2 + 1];
    float eg[8] = {ea.x, ea.y, ea.z, ea.w, eb.x, eb.y, eb.z, eb.w};

    float dot = 0.f, nrm = 0.f, egn = 0.f;
    #pragma unroll
    for (int k = 0; k < 8; ++k) {
        dot += acc[k] * eg[k];
        nrm += acc[k] * acc[k];
        if (FIRST) egn += eg[k] * eg[k];
    }
    #pragma unroll
    for (int o = 4; o; o >>= 1) {
        dot += __shfl_xor_sync(FULL, dot, o);
        nrm += __shfl_xor_sync(FULL, nrm, o);
        if (FIRST) egn += __shfl_xor_sync(FULL, egn, o);
    }

    float ego_norm;
    if (FIRST) {
        ego_norm = sqrtf(egn);
        if (hl == 0) g_norm[row] = ego_norm;
    } else {
        ego_norm = g_norm[row];
    }
    float w = dot / fmaxf(sqrtf(nrm) * ego_norm, EPS_);

    float r[8];
    #pragma unroll
    for (int k = 0; k < 8; ++k) r[k] = w * acc[k];

    if (LAST) {
        float s1[8], s2[8], s3[8];
        h16_to_f8(g_h1[row * 8 + hl], s1);
        h16_to_f8(g_h2[row * 8 + hl], s2);
        h16_to_f8(g_h3[row * 8 + hl], s3);
        float o0[8];
        #pragma unroll
        for (int k = 0; k < 8; ++k)
            o0[k] = eg[k] + s1[k] + s2[k] + s3[k] + r[k];
        out[row * 16 + hl * 2]     = make_float4(o0[0], o0[1], o0[2], o0[3]);
        out[row * 16 + hl * 2 + 1] = make_float4(o0[4], o0[5], o0[6], o0[7]);
    } else {
        xn[row * 8 + hl] = f8_to_h16(r);
    }
}

// ---------------- launch ----------------
extern "C" void kernel_launch(void* const* d_in, const int* in_sizes, int n_in,
                              void* d_out, int out_size)
{
    const float* user_fea = (const float*)d_in[0];
    const float* item_fea = (const float*)d_in[1];
    const float* prompt   = (const float*)d_in[2];
    const float* mlp_w    = (const float*)d_in[3];
    const float* mlp_b    = (const float*)d_in[4];
    const int*   adj_rows = (const int*)  d_in[5];
    const int*   adj_cols = (const int*)  d_in[6];
    const float* adj_vals = (const float*)d_in[7];
    float* out = (float*)d_out;

    static cudaStream_t s2 = nullptr;
    static cudaEvent_t  evFork = nullptr, evJoin = nullptr;
    if (s2 == nullptr) {
        cudaStreamCreateWithFlags(&s2, cudaStreamNonBlocking);
        cudaEventCreateWithFlags(&evFork, cudaEventDisableTiming);
        cudaEventCreateWithFlags(&evJoin, cudaEventDisableTiming);
    }

    uint4 *hEgo = nullptr, *h1 = nullptr, *h2 = nullptr, *h3 = nullptr;
    cudaGetSymbolAddress((void**)&hEgo, g_hEgo);
    cudaGetSymbolAddress((void**)&h1, g_h1);
    cudaGetSymbolAddress((void**)&h2, g_h2);
    cudaGetSymbolAddress((void**)&h3, g_h3);
    float4* out4 = (float4*)out;

    // ---- fork: CSR build on s2, embeddings on capture (default) stream ----
    cudaEventRecord(evFork, 0);
    cudaStreamWaitEvent(s2, evFork, 0);

    // branch A (default stream): embeddings
    k_user_ego<<<(N_USER * EMB + 255) / 256, 256>>>(user_fea, prompt);
    k_gemm    <<<(N_ITEM + 63) / 64, 256>>>(item_fea, mlp_w, mlp_b);

    // branch B (s2): CSR build (g_deg zero at entry; self-reset by k_scan1)
    k_hist    <<<(NNZ / 4 + 255) / 256, 256, 0, s2>>>((const int4*)adj_rows);
    k_scan1   <<<NB_SCAN, SCAN_BLK, 0, s2>>>();
    k_scan2   <<<1, 1024, 0, s2>>>();
    k_scan3   <<<(NTOT + 255) / 256, 256, 0, s2>>>();
    k_scatter <<<(NNZ / 4 + 255) / 256, 256, 0, s2>>>((const int4*)adj_rows,
                                                      (const int4*)adj_cols,
                                                      (const float4*)adj_vals);

    // ---- join ----
    cudaEventRecord(evJoin, s2);
    cudaStreamWaitEvent(0, evJoin, 0);

    // --- 4 propagation layers; last layer fuses the output epilogue ---
    int nwarp   = (NTOT + 3) / 4;                      // 4 rows per warp
    int pblocks = (nwarp * 32 + 255) / 256;
    k_prop<true,  false><<<pblocks, 256>>>(hEgo, h1, nullptr);
    k_prop<false, false><<<pblocks, 256>>>(h1,   h2, nullptr);
    k_prop<false, false><<<pblocks, 256>>>(h2,   h3, nullptr);
    k_prop<false, true ><<<pblocks, 256>>>(h3,   nullptr, out4);
}